// round 13
// baseline (speedup 1.0000x reference)
#include <cuda_runtime.h>
#include <cuda_fp16.h>
#include <math.h>
#include <stdint.h>

#define BATCH 2
#define SEQ   2048
#define DIM   2048
#define NHEAD 16
#define HDIM  128
#define MTOT  (BATCH * SEQ)
#define EPSV  1.1920928955078125e-07f
#define LOG2E 1.4426950408889634f

// fp16 operands / intermediates
__device__ __half g_xh[MTOT * DIM];
__device__ __half g_Wqh[DIM * DIM];   // rows permuted per head (rope pairing)
__device__ __half g_Wkh[DIM * DIM];
__device__ __half g_Wvh[DIM * DIM];
__device__ __half g_Woh[DIM * DIM];
__device__ __half g_Vh[MTOT * DIM];
__device__ __half g_Yh[MTOT * DIM];
__device__ __half g_Qh[MTOT * DIM];
__device__ __half g_Kh[MTOT * DIM];
__device__ float2 g_cs[SEQ * 64];

// ---------------------------------------------------------------------------
// Conversions + rope table in one launch:
// y<4 -> weights (Wq/Wk permuted), y==4 -> x, y==5 -> rope cos/sin table
// ---------------------------------------------------------------------------
__global__ void f2h_all(const float* __restrict__ x,
                        const float* __restrict__ w0, const float* __restrict__ w1,
                        const float* __restrict__ w2, const float* __restrict__ w3,
                        int nW4, int nX4)
{
    const int which = blockIdx.y;
    int i = blockIdx.x * blockDim.x + threadIdx.x;
    if (which == 5) {
        if (i >= SEQ * 64) return;
        int pos = i >> 6;
        int p   = i & 63;
        const float LN1E4 = 9.210340371976184f;
        float ang = (float)pos * __expf(-(float)p * (1.0f / 64.0f) * LN1E4);
        float sn, cn;
        sincosf(ang, &sn, &cn);
        g_cs[i] = make_float2(cn, sn);
        return;
    }
    const float* s;
    __half* d;
    if (which == 4) {
        if (i >= nX4) return;
        s = x; d = g_xh;
    } else {
        if (i >= nW4) return;
        s = (which == 0) ? w0 : (which == 1) ? w1 : (which == 2) ? w2 : w3;
        d = (which == 0) ? g_Wqh : (which == 1) ? g_Wkh
          : (which == 2) ? g_Wvh : g_Woh;
    }
    int src = i;
    if (which < 2) {
        int rd = i >> 9;
        int c4 = i & 511;
        int head = rd >> 7;
        int m = rd & 127;
        int od = (m & 1) ? (m >> 1) + 64 : (m >> 1);
        src = (head * 128 + od) * 512 + c4;
    }
    float4 v = ((const float4*)s)[src];
    __half2 a = __floats2half2_rn(v.x, v.y);
    __half2 b = __floats2half2_rn(v.z, v.w);
    uint2 o;
    o.x = *(uint32_t*)&a;
    o.y = *(uint32_t*)&b;
    ((uint2*)d)[i] = o;
}

// ---------------------------------------------------------------------------
// PTX helpers
// ---------------------------------------------------------------------------
__device__ __forceinline__ uint32_t smem_u32(const void* p) {
    uint32_t a;
    asm("{ .reg .u64 t; cvta.to.shared.u64 t, %1; cvt.u32.u64 %0, t; }"
        : "=r"(a) : "l"(p));
    return a;
}
#define CP_ASYNC(saddr, gaddr) \
    asm volatile("cp.async.cg.shared.global [%0], [%1], 16;" :: "r"(saddr), "l"(gaddr))
#define CP_COMMIT() asm volatile("cp.async.commit_group;" ::: "memory")
#define CP_WAIT2()  asm volatile("cp.async.wait_group 2;" ::: "memory")
#define CP_WAIT1()  asm volatile("cp.async.wait_group 1;" ::: "memory")
#define CP_WAIT0()  asm volatile("cp.async.wait_group 0;" ::: "memory")
#define LDSM_X4(r0, r1, r2, r3, addr) \
    asm volatile("ldmatrix.sync.aligned.m8n8.x4.shared.b16 {%0,%1,%2,%3}, [%4];" \
        : "=r"(r0), "=r"(r1), "=r"(r2), "=r"(r3) : "r"(addr))
#define LDSM_X4_T(r0, r1, r2, r3, addr) \
    asm volatile("ldmatrix.sync.aligned.m8n8.x4.trans.shared.b16 {%0,%1,%2,%3}, [%4];" \
        : "=r"(r0), "=r"(r1), "=r"(r2), "=r"(r3) : "r"(addr))
#define MMA_F16(c, a0, a1, a2, a3, b0, b1) \
    asm volatile("mma.sync.aligned.m16n8k16.row.col.f32.f16.f16.f32 " \
        "{%0,%1,%2,%3}, {%4,%5,%6,%7}, {%8,%9}, {%0,%1,%2,%3};" \
        : "+f"((c)[0]), "+f"((c)[1]), "+f"((c)[2]), "+f"((c)[3]) \
        : "r"(a0), "r"(a1), "r"(a2), "r"(a3), "r"(b0), "r"(b1))

__device__ __forceinline__ uint32_t packh2(float x, float y) {
    __half2 h = __floats2half2_rn(x, y);
    return *(uint32_t*)&h;
}

// ===========================================================================
// fp16 GEMM (champion config, unchanged): block 128x128, BK=32, 8 warps (4x2),
// warp tile 32x64, 3-stage cp.async, single barrier per k-iter.
// ===========================================================================
#define BK       32
#define ROWP     40
#define STAGE_H  (128 * ROWP)
#define NSTAGE   3
#define SMEM_BYTES (NSTAGE * 2 * STAGE_H * 2)   // 61440

__device__ __forceinline__ void gemm_issue(const __half* __restrict__ A,
                                           const __half* __restrict__ B,
                                           uint32_t sA, uint32_t sB,
                                           int m0, int n0, int kt, int tid)
{
    const int row = tid >> 1;
    const int cb  = (tid & 1) * 2;
#pragma unroll
    for (int c = 0; c < 2; c++) {
        int col = (cb + c) * 8;
        CP_ASYNC(sA + (row * ROWP + col) * 2,
                 A + (size_t)(m0 + row) * DIM + kt * BK + col);
        CP_ASYNC(sB + (row * ROWP + col) * 2,
                 B + (size_t)(n0 + row) * DIM + kt * BK + col);
    }
    CP_COMMIT();
}

__device__ __forceinline__ void gemm_compute(uint32_t sA, uint32_t sB,
                                             float c[2][8][4],
                                             int wm, int wn, int lane)
{
    const int grp = lane >> 3;
    const int li  = lane & 7;
    const int arow = wm * 32 + (grp & 1) * 8 + li;
    const int akof = (grp >> 1) * 8;
    const int brow = wn * 64 + (grp >> 1) * 8 + li;
    const int bkof = (grp & 1) * 8;

#pragma unroll
    for (int ks = 0; ks < 2; ks++) {
        uint32_t a[2][4];
        uint32_t b[4][4];
#pragma unroll
        for (int i = 0; i < 2; i++)
            LDSM_X4(a[i][0], a[i][1], a[i][2], a[i][3],
                    sA + ((arow + i * 16) * ROWP + ks * 16 + akof) * 2);
#pragma unroll
        for (int p = 0; p < 4; p++)
            LDSM_X4(b[p][0], b[p][1], b[p][2], b[p][3],
                    sB + ((brow + p * 16) * ROWP + ks * 16 + bkof) * 2);
#pragma unroll
        for (int i = 0; i < 2; i++)
#pragma unroll
            for (int j = 0; j < 8; j++)
                MMA_F16(c[i][j], a[i][0], a[i][1], a[i][2], a[i][3],
                        b[j >> 1][(j & 1) * 2 + 0], b[j >> 1][(j & 1) * 2 + 1]);
    }
}

// MODE 0: fp32 out; MODE 1: fp16 out; MODE 2: fp16 out + RMSNorm + RoPE
template <int MODE>
__device__ __forceinline__ void gemm_body(const __half* __restrict__ A,
                                          const __half* __restrict__ B,
                                          float* __restrict__ C,
                                          __half* __restrict__ Ch,
                                          float oscale,
                                          const float2* __restrict__ cs,
                                          int m0, int n0)
{
    extern __shared__ __half sh[];
    const int tid  = threadIdx.x;
    const int lane = tid & 31;
    const int wid  = tid >> 5;
    const int wm   = wid >> 1;
    const int wn   = wid & 1;

    uint32_t sA[NSTAGE], sB[NSTAGE];
#pragma unroll
    for (int s = 0; s < NSTAGE; s++) {
        sA[s] = smem_u32(sh + s * 2 * STAGE_H);
        sB[s] = smem_u32(sh + s * 2 * STAGE_H + STAGE_H);
    }

    float c[2][8][4];
#pragma unroll
    for (int i = 0; i < 2; i++)
#pragma unroll
        for (int j = 0; j < 8; j++)
#pragma unroll
            for (int e = 0; e < 4; e++) c[i][j][e] = 0.0f;

    const int NIT = DIM / BK;   // 64

    gemm_issue(A, B, sA[0], sB[0], m0, n0, 0, tid);
    gemm_issue(A, B, sA[1], sB[1], m0, n0, 1, tid);

#pragma unroll 1
    for (int kt = 0; kt < NIT; kt++) {
        if (kt + 2 < NIT) CP_WAIT1(); else CP_WAIT0();
        __syncthreads();
        if (kt + 2 < NIT)
            gemm_issue(A, B, sA[(kt + 2) % 3], sB[(kt + 2) % 3],
                       m0, n0, kt + 2, tid);
        gemm_compute(sA[kt % 3], sB[kt % 3], c, wm, wn, lane);
    }

    const int g = lane >> 2;
    const int t = lane & 3;

    if (MODE == 2) {
        __syncthreads();
        float* fss = (float*)sh;
        float ssp[2][2];
#pragma unroll
        for (int i = 0; i < 2; i++) {
            float slo = 0.f, shi = 0.f;
#pragma unroll
            for (int j = 0; j < 8; j++) {
                slo += c[i][j][0] * c[i][j][0] + c[i][j][1] * c[i][j][1];
                shi += c[i][j][2] * c[i][j][2] + c[i][j][3] * c[i][j][3];
            }
            slo += __shfl_xor_sync(0xffffffffu, slo, 1);
            slo += __shfl_xor_sync(0xffffffffu, slo, 2);
            shi += __shfl_xor_sync(0xffffffffu, shi, 1);
            shi += __shfl_xor_sync(0xffffffffu, shi, 2);
            ssp[i][0] = slo; ssp[i][1] = shi;
        }
        if (t == 0) {
#pragma unroll
            for (int i = 0; i < 2; i++) {
                int rb = wm * 32 + i * 16 + g;
                fss[wn * 128 + rb]     = ssp[i][0];
                fss[wn * 128 + rb + 8] = ssp[i][1];
            }
        }
        __syncthreads();
#pragma unroll
        for (int i = 0; i < 2; i++) {
            int rlo = wm * 32 + i * 16 + g;
            int rhi = rlo + 8;
            float rnlo = rsqrtf((fss[rlo] + fss[128 + rlo]) * (1.0f / 128.0f) + EPSV) * oscale;
            float rnhi = rsqrtf((fss[rhi] + fss[128 + rhi]) * (1.0f / 128.0f) + EPSV) * oscale;
            int poslo = (m0 + rlo) & (SEQ - 1);
            int poshi = (m0 + rhi) & (SEQ - 1);
#pragma unroll
            for (int j = 0; j < 8; j++) {
                int dp = wn * 32 + j * 4 + t;
                int ncol = n0 + wn * 64 + j * 8 + t * 2;
                float2 cl = cs[poslo * 64 + dp];
                float x1 = c[i][j][0] * rnlo, x2 = c[i][j][1] * rnlo;
                uint32_t olo = packh2(x1 * cl.x + x2 * cl.y,
                                      -x1 * cl.y + x2 * cl.x);
                *(uint32_t*)&Ch[(size_t)(m0 + rlo) * DIM + ncol] = olo;
                float2 ch2 = cs[poshi * 64 + dp];
                float y1 = c[i][j][2] * rnhi, y2 = c[i][j][3] * rnhi;
                uint32_t ohi = packh2(y1 * ch2.x + y2 * ch2.y,
                                      -y1 * ch2.y + y2 * ch2.x);
                *(uint32_t*)&Ch[(size_t)(m0 + rhi) * DIM + ncol] = ohi;
            }
        }
        return;
    }

#pragma unroll
    for (int i = 0; i < 2; i++) {
        int mbase = m0 + wm * 32 + i * 16;
#pragma unroll
        for (int j = 0; j < 8; j++) {
            int ncol = n0 + wn * 64 + j * 8 + t * 2;
            if (MODE == 1) {
                uint32_t lo = packh2(c[i][j][0], c[i][j][1]);
                uint32_t hi = packh2(c[i][j][2], c[i][j][3]);
                *(uint32_t*)&Ch[(size_t)(mbase + g) * DIM + ncol]     = lo;
                *(uint32_t*)&Ch[(size_t)(mbase + g + 8) * DIM + ncol] = hi;
            } else {
                *(float2*)&C[(size_t)(mbase + g) * DIM + ncol] =
                    make_float2(c[i][j][0], c[i][j][1]);
                *(float2*)&C[(size_t)(mbase + g + 8) * DIM + ncol] =
                    make_float2(c[i][j][2], c[i][j][3]);
            }
        }
    }
}

// QKV fused: grid.x = 48: [0,16)->Q, [16,32)->K, [32,48)->V
__global__ __launch_bounds__(256, 2) void gemm_qkv(const __half* __restrict__ xh,
                                                   const float2* __restrict__ cs)
{
    const int which = blockIdx.x >> 4;
    const int n0 = (blockIdx.x & 15) * 128;
    const int m0 = blockIdx.y * 128;
    const float QSC = 0.08838834764831845f * LOG2E;
    if (which == 0)
        gemm_body<2>(xh, g_Wqh, nullptr, g_Qh, QSC, cs, m0, n0);
    else if (which == 1)
        gemm_body<2>(xh, g_Wkh, nullptr, g_Kh, 1.0f, cs, m0, n0);
    else
        gemm_body<1>(xh, g_Wvh, nullptr, g_Vh, 1.0f, nullptr, m0, n0);
}

__global__ __launch_bounds__(256, 2) void gemm_nt(const __half* __restrict__ A,
                                                  const __half* __restrict__ B,
                                                  float* __restrict__ C)
{
    gemm_body<0>(A, B, C, nullptr, 1.0f, nullptr, blockIdx.y * 128, blockIdx.x * 128);
}

// ===========================================================================
// Tensor-core causal flash attention: 64 q-rows/CTA, 4 warps, BN=32,
// 3-buffer K/V pipeline (wait<=2), 3 CTAs/SM. Heavy-first order,
// Q fragments in registers, row sums via all-ones MMA.
// ===========================================================================
#define BN2    32
#define ROWQ   136
#define A_QH   (64 * ROWQ)                 // Q halves: 8704
#define A_KH   (32 * ROWQ)                 // K/V tile halves: 4352
#define ATT_SMEM ((A_QH + 6 * A_KH) * 2)   // 69632 bytes (3 K + 3 V buffers)

__global__ __launch_bounds__(128, 3) void attn_tc(const __half* __restrict__ Qh,
                                                  const __half* __restrict__ Kh,
                                                  const __half* __restrict__ Vh,
                                                  __half* __restrict__ Yh)
{
    extern __shared__ __half ash[];
    const int tid  = threadIdx.x;
    const int lane = tid & 31;
    const int wid  = tid >> 5;          // 0..3
    const int b = blockIdx.z;
    const int h = blockIdx.y;
    const int bx = (int)gridDim.x - 1 - (int)blockIdx.x;   // heavy blocks first
    const int m0 = bx * 64;
    const size_t bS = (size_t)b * SEQ;
    const uint32_t ONES = 0x3C003C00u;

    const uint32_t sQ = smem_u32(ash);
    uint32_t sK[3], sV[3];
#pragma unroll
    for (int s = 0; s < 3; s++) {
        sK[s] = smem_u32(ash + A_QH + s * A_KH);
        sV[s] = smem_u32(ash + A_QH + (3 + s) * A_KH);
    }

    const __half* Qg = Qh + (bS + m0) * DIM + h * HDIM;
    const __half* Kg = Kh + bS * DIM + h * HDIM;
    const __half* Vg = Vh + bS * DIM + h * HDIM;

    const int T = bx * 2 + 2;           // 32-key tiles (>=2 always)

    const int srow = tid >> 4;          // 0..7
    const int scq  = tid & 15;

    // prologue staging: Q + tile0 in group0; tiles 1,2 in their own groups
    {
#pragma unroll
        for (int i = 0; i < 8; i++) {   // Q: 64 rows
            int r = srow + i * 8;
            CP_ASYNC(sQ + (r * ROWQ + scq * 8) * 2, Qg + (size_t)r * DIM + scq * 8);
        }
#pragma unroll
        for (int i = 0; i < 4; i++) {   // K/V tile 0
            int r = srow + i * 8;
            CP_ASYNC(sK[0] + (r * ROWQ + scq * 8) * 2, Kg + (size_t)r * DIM + scq * 8);
            CP_ASYNC(sV[0] + (r * ROWQ + scq * 8) * 2, Vg + (size_t)r * DIM + scq * 8);
        }
        CP_COMMIT();
    }
    int issued = 1;
#pragma unroll 1
    for (int pt = 1; pt < 3; pt++) {
        if (pt < T) {
            int nn = pt * BN2;
#pragma unroll
            for (int i = 0; i < 4; i++) {
                int r = srow + i * 8;
                CP_ASYNC(sK[pt] + (r * ROWQ + scq * 8) * 2,
                         Kg + (size_t)(nn + r) * DIM + scq * 8);
                CP_ASYNC(sV[pt] + (r * ROWQ + scq * 8) * 2,
                         Vg + (size_t)(nn + r) * DIM + scq * 8);
            }
            CP_COMMIT();
            issued++;
        }
    }

    const int grp = lane >> 3;
    const int li  = lane & 7;
    const int r0 = m0 + wid * 16 + (lane >> 2);
    const int r1 = r0 + 8;

    float Of[16][4];
#pragma unroll
    for (int j = 0; j < 16; j++)
#pragma unroll
        for (int e = 0; e < 4; e++) Of[j][e] = 0.0f;
    float mx0 = -1e30f, mx1 = -1e30f, l0 = 0.0f, l1 = 0.0f;

    const int vkey = ((lane >> 3) & 1) * 8 + (lane & 7);
    const int vdof = (lane >> 4) * 8;

    uint32_t qf[8][4];

#pragma unroll 1
    for (int t = 0; t < T; t++) {
        // tile t must be complete; allowed outstanding = issued - t - 1
        {
            int pend = issued - t - 1;
            if (pend >= 2) CP_WAIT2();
            else if (pend == 1) CP_WAIT1();
            else CP_WAIT0();
        }
        __syncthreads();

        if (t == 0) {
#pragma unroll
            for (int ks = 0; ks < 8; ks++)
                LDSM_X4(qf[ks][0], qf[ks][1], qf[ks][2], qf[ks][3],
                        sQ + (((wid * 16 + (grp & 1) * 8 + li)) * ROWQ
                              + ks * 16 + (grp >> 1) * 8) * 2);
        }

        const int n0 = t * BN2;
        const int buf = t % 3;
        if (n0 <= m0 + wid * 16 + 15) {
            const uint32_t kb = sK[buf];
            const uint32_t vb = sV[buf];

            float sf[4][4];
#pragma unroll
            for (int f = 0; f < 4; f++)
#pragma unroll
                for (int e = 0; e < 4; e++) sf[f][e] = 0.0f;

            // S = Q K^T (32 keys)
#pragma unroll
            for (int ks = 0; ks < 8; ks++) {
#pragma unroll
                for (int p = 0; p < 2; p++) {
                    uint32_t b0, b1, b2, b3;
                    LDSM_X4(b0, b1, b2, b3,
                            kb + (((grp >> 1) * 8 + li + p * 16) * ROWQ
                                  + ks * 16 + (grp & 1) * 8) * 2);
                    MMA_F16(sf[2 * p],     qf[ks][0], qf[ks][1], qf[ks][2], qf[ks][3], b0, b1);
                    MMA_F16(sf[2 * p + 1], qf[ks][0], qf[ks][1], qf[ks][2], qf[ks][3], b2, b3);
                }
            }

            // causal mask
            if (n0 + 31 > m0 + wid * 16) {
#pragma unroll
                for (int f = 0; f < 4; f++) {
                    int c0 = n0 + f * 8 + (lane & 3) * 2;
                    if (c0 > r0)     sf[f][0] = -1e30f;
                    if (c0 + 1 > r0) sf[f][1] = -1e30f;
                    if (c0 > r1)     sf[f][2] = -1e30f;
                    if (c0 + 1 > r1) sf[f][3] = -1e30f;
                }
            }

            float mt0 = -1e30f, mt1 = -1e30f;
#pragma unroll
            for (int f = 0; f < 4; f++) {
                mt0 = fmaxf(mt0, fmaxf(sf[f][0], sf[f][1]));
                mt1 = fmaxf(mt1, fmaxf(sf[f][2], sf[f][3]));
            }
            mt0 = fmaxf(mt0, __shfl_xor_sync(0xffffffffu, mt0, 1));
            mt0 = fmaxf(mt0, __shfl_xor_sync(0xffffffffu, mt0, 2));
            mt1 = fmaxf(mt1, __shfl_xor_sync(0xffffffffu, mt1, 1));
            mt1 = fmaxf(mt1, __shfl_xor_sync(0xffffffffu, mt1, 2));

            float mn0 = fmaxf(mx0, mt0);
            float mn1 = fmaxf(mx1, mt1);
            float al0 = exp2f(mx0 - mn0);
            float al1 = exp2f(mx1 - mn1);
            mx0 = mn0; mx1 = mn1;

#pragma unroll
            for (int f = 0; f < 4; f++) {
                sf[f][0] = exp2f(sf[f][0] - mn0);
                sf[f][1] = exp2f(sf[f][1] - mn0);
                sf[f][2] = exp2f(sf[f][2] - mn1);
                sf[f][3] = exp2f(sf[f][3] - mn1);
            }

            uint32_t p16[8];
            float lacc[4] = {0.f, 0.f, 0.f, 0.f};
#pragma unroll
            for (int ks2 = 0; ks2 < 2; ks2++) {
                uint32_t pa0 = packh2(sf[2 * ks2][0],     sf[2 * ks2][1]);
                uint32_t pa1 = packh2(sf[2 * ks2][2],     sf[2 * ks2][3]);
                uint32_t pa2 = packh2(sf[2 * ks2 + 1][0], sf[2 * ks2 + 1][1]);
                uint32_t pa3 = packh2(sf[2 * ks2 + 1][2], sf[2 * ks2 + 1][3]);
                p16[ks2 * 4 + 0] = pa0; p16[ks2 * 4 + 1] = pa1;
                p16[ks2 * 4 + 2] = pa2; p16[ks2 * 4 + 3] = pa3;
                MMA_F16(lacc, pa0, pa1, pa2, pa3, ONES, ONES);
            }
            l0 = l0 * al0 + lacc[0];
            l1 = l1 * al1 + lacc[2];

#pragma unroll
            for (int j = 0; j < 16; j++) {
                Of[j][0] *= al0; Of[j][1] *= al0;
                Of[j][2] *= al1; Of[j][3] *= al1;
            }

            // O += P V
#pragma unroll
            for (int ks2 = 0; ks2 < 2; ks2++) {
#pragma unroll
                for (int p = 0; p < 8; p++) {
                    uint32_t b0, b1, b2, b3;
                    LDSM_X4_T(b0, b1, b2, b3,
                              vb + ((ks2 * 16 + vkey) * ROWQ + p * 16 + vdof) * 2);
                    MMA_F16(Of[2 * p],     p16[ks2 * 4 + 0], p16[ks2 * 4 + 1],
                            p16[ks2 * 4 + 2], p16[ks2 * 4 + 3], b0, b1);
                    MMA_F16(Of[2 * p + 1], p16[ks2 * 4 + 0], p16[ks2 * 4 + 1],
                            p16[ks2 * 4 + 2], p16[ks2 * 4 + 3], b2, b3);
                }
            }
        }

        __syncthreads();
        if (issued < T) {
            const int nn = issued * BN2;
            const int ib = issued % 3;
#pragma unroll
            for (int i = 0; i < 4; i++) {
                int r = srow + i * 8;
                CP_ASYNC(sK[ib] + (r * ROWQ + scq * 8) * 2,
                         Kg + (size_t)(nn + r) * DIM + scq * 8);
                CP_ASYNC(sV[ib] + (r * ROWQ + scq * 8) * 2,
                         Vg + (size_t)(nn + r) * DIM + scq * 8);
            }
            CP_COMMIT();
            issued++;
        }
    }

    float inv0 = 1.0f / l0;
    float inv1 = 1.0f / l1;
#pragma unroll
    for (int j = 0; j < 16; j++) {
        int c = h * HDIM + j * 8 + (lane & 3) * 2;
        __half2 o0 = __floats2half2_rn(Of[j][0] * inv0, Of[j][1] * inv0);
        __half2 o1 = __floats2half2_rn(Of[j][2] * inv1, Of[j][3] * inv1);
        *(uint32_t*)&Yh[(bS + r0) * DIM + c] = *(uint32_t*)&o0;
        *(uint32_t*)&Yh[(bS + r1) * DIM + c] = *(uint32_t*)&o1;
    }
}

// ---------------------------------------------------------------------------
extern "C" void kernel_launch(void* const* d_in, const int* in_sizes, int n_in,
                              void* d_out, int out_size)
{
    const float* x  = (const float*)d_in[0];
    const float* Wq = (const float*)d_in[1];
    const float* Wk = (const float*)d_in[2];
    const float* Wv = (const float*)d_in[3];
    const float* Wo = (const float*)d_in[4];
    float* out = (float*)d_out;

    __half* xh;  cudaGetSymbolAddress((void**)&xh,  g_xh);
    __half* woh; cudaGetSymbolAddress((void**)&woh, g_Woh);
    __half* vh;  cudaGetSymbolAddress((void**)&vh,  g_Vh);
    __half* yh;  cudaGetSymbolAddress((void**)&yh,  g_Yh);
    __half* qh;  cudaGetSymbolAddress((void**)&qh,  g_Qh);
    __half* kh;  cudaGetSymbolAddress((void**)&kh,  g_Kh);
    float2* cs;  cudaGetSymbolAddress((void**)&cs,  g_cs);

    cudaFuncSetAttribute(gemm_qkv, cudaFuncAttributeMaxDynamicSharedMemorySize, SMEM_BYTES);
    cudaFuncSetAttribute(gemm_nt,  cudaFuncAttributeMaxDynamicSharedMemorySize, SMEM_BYTES);
    cudaFuncSetAttribute(attn_tc,  cudaFuncAttributeMaxDynamicSharedMemorySize, ATT_SMEM);

    const int nW4 = DIM * DIM / 4;
    const int nX4 = MTOT * DIM / 4;
    f2h_all<<<dim3((nX4 + 255) / 256, 6), 256>>>(x, Wq, Wk, Wv, Wo, nW4, nX4);

    dim3 gQKV(48, MTOT / 128);
    gemm_qkv<<<gQKV, 256, SMEM_BYTES>>>(xh, cs);

    dim3 gAttn(SEQ / 64, NHEAD, BATCH);    // (32, 16, 2) = 1024 CTAs
    attn_tc<<<gAttn, 128, ATT_SMEM>>>(qh, kh, vh, yh);

    dim3 gO(DIM / 128, MTOT / 128);
    gemm_nt<<<gO, 256, SMEM_BYTES>>>(yh, woh, out);
}

// round 14
// speedup vs baseline: 1.0111x; 1.0111x over previous
#include <cuda_runtime.h>
#include <cuda_fp16.h>
#include <math.h>
#include <stdint.h>

#define BATCH 2
#define SEQ   2048
#define DIM   2048
#define NHEAD 16
#define HDIM  128
#define MTOT  (BATCH * SEQ)
#define EPSV  1.1920928955078125e-07f
#define LOG2E 1.4426950408889634f

// fp16 operands / intermediates
__device__ __half g_xh[MTOT * DIM];
__device__ __half g_Wqh[DIM * DIM];   // rows permuted per head (rope pairing)
__device__ __half g_Wkh[DIM * DIM];
__device__ __half g_Wvh[DIM * DIM];
__device__ __half g_Woh[DIM * DIM];
__device__ __half g_Vh[MTOT * DIM];
__device__ __half g_Yh[MTOT * DIM];
__device__ __half g_Qh[MTOT * DIM];
__device__ __half g_Kh[MTOT * DIM];
__device__ float2 g_cs[SEQ * 64];

// ---------------------------------------------------------------------------
// Conversions + rope table, 4 float4 per thread (MLP=4):
// y<4 -> weights (Wq/Wk permuted), y==4 -> x, y==5 -> rope cos/sin table
// ---------------------------------------------------------------------------
__global__ void f2h_all(const float* __restrict__ x,
                        const float* __restrict__ w0, const float* __restrict__ w1,
                        const float* __restrict__ w2, const float* __restrict__ w3,
                        int nW4, int nX4)
{
    const int which = blockIdx.y;
    const int stride = gridDim.x * blockDim.x;
    const int base = blockIdx.x * blockDim.x + threadIdx.x;

    if (which == 5) {
#pragma unroll
        for (int k = 0; k < 4; k++) {
            int i = base + k * stride;
            if (i >= SEQ * 64) break;
            int pos = i >> 6;
            int p   = i & 63;
            const float LN1E4 = 9.210340371976184f;
            float ang = (float)pos * __expf(-(float)p * (1.0f / 64.0f) * LN1E4);
            float sn, cn;
            sincosf(ang, &sn, &cn);
            g_cs[i] = make_float2(cn, sn);
        }
        return;
    }

    const float* s;
    __half* d;
    int n4;
    if (which == 4) {
        s = x; d = g_xh; n4 = nX4;
    } else {
        s = (which == 0) ? w0 : (which == 1) ? w1 : (which == 2) ? w2 : w3;
        d = (which == 0) ? g_Wqh : (which == 1) ? g_Wkh
          : (which == 2) ? g_Wvh : g_Woh;
        n4 = nW4;
    }

    // gather 4 independent float4 loads first (MLP), then convert+store
    float4 v[4];
    int idx[4];
    int cnt = 0;
#pragma unroll
    for (int k = 0; k < 4; k++) {
        int i = base + k * stride;
        if (i < n4) {
            int src = i;
            if (which < 2) {
                int rd = i >> 9;
                int c4 = i & 511;
                int head = rd >> 7;
                int m = rd & 127;
                int od = (m & 1) ? (m >> 1) + 64 : (m >> 1);
                src = (head * 128 + od) * 512 + c4;
            }
            v[cnt] = ((const float4*)s)[src];
            idx[cnt] = i;
            cnt++;
        }
    }
#pragma unroll
    for (int k = 0; k < 4; k++) {
        if (k < cnt) {
            __half2 a = __floats2half2_rn(v[k].x, v[k].y);
            __half2 b = __floats2half2_rn(v[k].z, v[k].w);
            uint2 o;
            o.x = *(uint32_t*)&a;
            o.y = *(uint32_t*)&b;
            ((uint2*)d)[idx[k]] = o;
        }
    }
}

// ---------------------------------------------------------------------------
// PTX helpers
// ---------------------------------------------------------------------------
__device__ __forceinline__ uint32_t smem_u32(const void* p) {
    uint32_t a;
    asm("{ .reg .u64 t; cvta.to.shared.u64 t, %1; cvt.u32.u64 %0, t; }"
        : "=r"(a) : "l"(p));
    return a;
}
#define CP_ASYNC(saddr, gaddr) \
    asm volatile("cp.async.cg.shared.global [%0], [%1], 16;" :: "r"(saddr), "l"(gaddr))
#define CP_COMMIT() asm volatile("cp.async.commit_group;" ::: "memory")
#define CP_WAIT1()  asm volatile("cp.async.wait_group 1;" ::: "memory")
#define CP_WAIT0()  asm volatile("cp.async.wait_group 0;" ::: "memory")
#define LDSM_X4(r0, r1, r2, r3, addr) \
    asm volatile("ldmatrix.sync.aligned.m8n8.x4.shared.b16 {%0,%1,%2,%3}, [%4];" \
        : "=r"(r0), "=r"(r1), "=r"(r2), "=r"(r3) : "r"(addr))
#define LDSM_X4_T(r0, r1, r2, r3, addr) \
    asm volatile("ldmatrix.sync.aligned.m8n8.x4.trans.shared.b16 {%0,%1,%2,%3}, [%4];" \
        : "=r"(r0), "=r"(r1), "=r"(r2), "=r"(r3) : "r"(addr))
#define MMA_F16(c, a0, a1, a2, a3, b0, b1) \
    asm volatile("mma.sync.aligned.m16n8k16.row.col.f32.f16.f16.f32 " \
        "{%0,%1,%2,%3}, {%4,%5,%6,%7}, {%8,%9}, {%0,%1,%2,%3};" \
        : "+f"((c)[0]), "+f"((c)[1]), "+f"((c)[2]), "+f"((c)[3]) \
        : "r"(a0), "r"(a1), "r"(a2), "r"(a3), "r"(b0), "r"(b1))

__device__ __forceinline__ uint32_t packh2(float x, float y) {
    __half2 h = __floats2half2_rn(x, y);
    return *(uint32_t*)&h;
}

// ===========================================================================
// fp16 GEMM (champion config): block 128x128, BK=32, 8 warps (4x2),
// warp tile 32x64, 3-stage cp.async, single barrier per k-iter.
// ===========================================================================
#define BK       32
#define ROWP     40
#define STAGE_H  (128 * ROWP)
#define NSTAGE   3
#define SMEM_BYTES (NSTAGE * 2 * STAGE_H * 2)   // 61440

__device__ __forceinline__ void gemm_issue(const __half* __restrict__ A,
                                           const __half* __restrict__ B,
                                           uint32_t sA, uint32_t sB,
                                           int m0, int n0, int kt, int tid)
{
    const int row = tid >> 1;
    const int cb  = (tid & 1) * 2;
#pragma unroll
    for (int c = 0; c < 2; c++) {
        int col = (cb + c) * 8;
        CP_ASYNC(sA + (row * ROWP + col) * 2,
                 A + (size_t)(m0 + row) * DIM + kt * BK + col);
        CP_ASYNC(sB + (row * ROWP + col) * 2,
                 B + (size_t)(n0 + row) * DIM + kt * BK + col);
    }
    CP_COMMIT();
}

__device__ __forceinline__ void gemm_compute(uint32_t sA, uint32_t sB,
                                             float c[2][8][4],
                                             int wm, int wn, int lane)
{
    const int grp = lane >> 3;
    const int li  = lane & 7;
    const int arow = wm * 32 + (grp & 1) * 8 + li;
    const int akof = (grp >> 1) * 8;
    const int brow = wn * 64 + (grp >> 1) * 8 + li;
    const int bkof = (grp & 1) * 8;

#pragma unroll
    for (int ks = 0; ks < 2; ks++) {
        uint32_t a[2][4];
        uint32_t b[4][4];
#pragma unroll
        for (int i = 0; i < 2; i++)
            LDSM_X4(a[i][0], a[i][1], a[i][2], a[i][3],
                    sA + ((arow + i * 16) * ROWP + ks * 16 + akof) * 2);
#pragma unroll
        for (int p = 0; p < 4; p++)
            LDSM_X4(b[p][0], b[p][1], b[p][2], b[p][3],
                    sB + ((brow + p * 16) * ROWP + ks * 16 + bkof) * 2);
#pragma unroll
        for (int i = 0; i < 2; i++)
#pragma unroll
            for (int j = 0; j < 8; j++)
                MMA_F16(c[i][j], a[i][0], a[i][1], a[i][2], a[i][3],
                        b[j >> 1][(j & 1) * 2 + 0], b[j >> 1][(j & 1) * 2 + 1]);
    }
}

// MODE 0: fp32 out; MODE 1: fp16 out; MODE 2: fp16 out + RMSNorm + RoPE
template <int MODE>
__device__ __forceinline__ void gemm_body(const __half* __restrict__ A,
                                          const __half* __restrict__ B,
                                          float* __restrict__ C,
                                          __half* __restrict__ Ch,
                                          float oscale,
                                          const float2* __restrict__ cs,
                                          int m0, int n0)
{
    extern __shared__ __half sh[];
    const int tid  = threadIdx.x;
    const int lane = tid & 31;
    const int wid  = tid >> 5;
    const int wm   = wid >> 1;
    const int wn   = wid & 1;

    uint32_t sA[NSTAGE], sB[NSTAGE];
#pragma unroll
    for (int s = 0; s < NSTAGE; s++) {
        sA[s] = smem_u32(sh + s * 2 * STAGE_H);
        sB[s] = smem_u32(sh + s * 2 * STAGE_H + STAGE_H);
    }

    float c[2][8][4];
#pragma unroll
    for (int i = 0; i < 2; i++)
#pragma unroll
        for (int j = 0; j < 8; j++)
#pragma unroll
            for (int e = 0; e < 4; e++) c[i][j][e] = 0.0f;

    const int NIT = DIM / BK;   // 64

    gemm_issue(A, B, sA[0], sB[0], m0, n0, 0, tid);
    gemm_issue(A, B, sA[1], sB[1], m0, n0, 1, tid);

#pragma unroll 1
    for (int kt = 0; kt < NIT; kt++) {
        if (kt + 2 < NIT) CP_WAIT1(); else CP_WAIT0();
        __syncthreads();
        if (kt + 2 < NIT)
            gemm_issue(A, B, sA[(kt + 2) % 3], sB[(kt + 2) % 3],
                       m0, n0, kt + 2, tid);
        gemm_compute(sA[kt % 3], sB[kt % 3], c, wm, wn, lane);
    }

    const int g = lane >> 2;
    const int t = lane & 3;

    if (MODE == 2) {
        __syncthreads();
        float* fss = (float*)sh;
        float ssp[2][2];
#pragma unroll
        for (int i = 0; i < 2; i++) {
            float slo = 0.f, shi = 0.f;
#pragma unroll
            for (int j = 0; j < 8; j++) {
                slo += c[i][j][0] * c[i][j][0] + c[i][j][1] * c[i][j][1];
                shi += c[i][j][2] * c[i][j][2] + c[i][j][3] * c[i][j][3];
            }
            slo += __shfl_xor_sync(0xffffffffu, slo, 1);
            slo += __shfl_xor_sync(0xffffffffu, slo, 2);
            shi += __shfl_xor_sync(0xffffffffu, shi, 1);
            shi += __shfl_xor_sync(0xffffffffu, shi, 2);
            ssp[i][0] = slo; ssp[i][1] = shi;
        }
        if (t == 0) {
#pragma unroll
            for (int i = 0; i < 2; i++) {
                int rb = wm * 32 + i * 16 + g;
                fss[wn * 128 + rb]     = ssp[i][0];
                fss[wn * 128 + rb + 8] = ssp[i][1];
            }
        }
        __syncthreads();
#pragma unroll
        for (int i = 0; i < 2; i++) {
            int rlo = wm * 32 + i * 16 + g;
            int rhi = rlo + 8;
            float rnlo = rsqrtf((fss[rlo] + fss[128 + rlo]) * (1.0f / 128.0f) + EPSV) * oscale;
            float rnhi = rsqrtf((fss[rhi] + fss[128 + rhi]) * (1.0f / 128.0f) + EPSV) * oscale;
            int poslo = (m0 + rlo) & (SEQ - 1);
            int poshi = (m0 + rhi) & (SEQ - 1);
#pragma unroll
            for (int j = 0; j < 8; j++) {
                int dp = wn * 32 + j * 4 + t;
                int ncol = n0 + wn * 64 + j * 8 + t * 2;
                float2 cl = cs[poslo * 64 + dp];
                float x1 = c[i][j][0] * rnlo, x2 = c[i][j][1] * rnlo;
                uint32_t olo = packh2(x1 * cl.x + x2 * cl.y,
                                      -x1 * cl.y + x2 * cl.x);
                *(uint32_t*)&Ch[(size_t)(m0 + rlo) * DIM + ncol] = olo;
                float2 ch2 = cs[poshi * 64 + dp];
                float y1 = c[i][j][2] * rnhi, y2 = c[i][j][3] * rnhi;
                uint32_t ohi = packh2(y1 * ch2.x + y2 * ch2.y,
                                      -y1 * ch2.y + y2 * ch2.x);
                *(uint32_t*)&Ch[(size_t)(m0 + rhi) * DIM + ncol] = ohi;
            }
        }
        return;
    }

#pragma unroll
    for (int i = 0; i < 2; i++) {
        int mbase = m0 + wm * 32 + i * 16;
#pragma unroll
        for (int j = 0; j < 8; j++) {
            int ncol = n0 + wn * 64 + j * 8 + t * 2;
            if (MODE == 1) {
                uint32_t lo = packh2(c[i][j][0], c[i][j][1]);
                uint32_t hi = packh2(c[i][j][2], c[i][j][3]);
                *(uint32_t*)&Ch[(size_t)(mbase + g) * DIM + ncol]     = lo;
                *(uint32_t*)&Ch[(size_t)(mbase + g + 8) * DIM + ncol] = hi;
            } else {
                *(float2*)&C[(size_t)(mbase + g) * DIM + ncol] =
                    make_float2(c[i][j][0], c[i][j][1]);
                *(float2*)&C[(size_t)(mbase + g + 8) * DIM + ncol] =
                    make_float2(c[i][j][2], c[i][j][3]);
            }
        }
    }
}

// QKV fused: grid.x = 48: [0,16)->Q, [16,32)->K, [32,48)->V
__global__ __launch_bounds__(256, 2) void gemm_qkv(const __half* __restrict__ xh,
                                                   const float2* __restrict__ cs)
{
    const int which = blockIdx.x >> 4;
    const int n0 = (blockIdx.x & 15) * 128;
    const int m0 = blockIdx.y * 128;
    const float QSC = 0.08838834764831845f * LOG2E;
    if (which == 0)
        gemm_body<2>(xh, g_Wqh, nullptr, g_Qh, QSC, cs, m0, n0);
    else if (which == 1)
        gemm_body<2>(xh, g_Wkh, nullptr, g_Kh, 1.0f, cs, m0, n0);
    else
        gemm_body<1>(xh, g_Wvh, nullptr, g_Vh, 1.0f, nullptr, m0, n0);
}

__global__ __launch_bounds__(256, 2) void gemm_nt(const __half* __restrict__ A,
                                                  const __half* __restrict__ B,
                                                  float* __restrict__ C)
{
    gemm_body<0>(A, B, C, nullptr, 1.0f, nullptr, blockIdx.y * 128, blockIdx.x * 128);
}

// ===========================================================================
// Tensor-core causal flash attention (R12 champion): 64 q-rows/CTA, 4 warps,
// BN=32 double-buffered, 3 CTAs/SM. Heavy-first order, Q frags in registers,
// row sums via all-ones MMA.
// ===========================================================================
#define BN2    32
#define ROWQ   136
#define A_QH   (64 * ROWQ)
#define A_KH   (32 * ROWQ)
#define A_K0   (A_QH)
#define A_K1   (A_QH + A_KH)
#define A_V0   (A_QH + 2 * A_KH)
#define A_V1   (A_QH + 3 * A_KH)
#define ATT_SMEM ((A_QH + 4 * A_KH) * 2)   // 52224 bytes

__global__ __launch_bounds__(128, 3) void attn_tc(const __half* __restrict__ Qh,
                                                  const __half* __restrict__ Kh,
                                                  const __half* __restrict__ Vh,
                                                  __half* __restrict__ Yh)
{
    extern __shared__ __half ash[];
    const int tid  = threadIdx.x;
    const int lane = tid & 31;
    const int wid  = tid >> 5;
    const int b = blockIdx.z;
    const int h = blockIdx.y;
    const int bx = (int)gridDim.x - 1 - (int)blockIdx.x;
    const int m0 = bx * 64;
    const size_t bS = (size_t)b * SEQ;
    const uint32_t ONES = 0x3C003C00u;

    const uint32_t sQ = smem_u32(ash);
    uint32_t sK[2] = { smem_u32(ash + A_K0), smem_u32(ash + A_K1) };
    uint32_t sV[2] = { smem_u32(ash + A_V0), smem_u32(ash + A_V1) };

    const __half* Qg = Qh + (bS + m0) * DIM + h * HDIM;
    const __half* Kg = Kh + bS * DIM + h * HDIM;
    const __half* Vg = Vh + bS * DIM + h * HDIM;

    const int T = bx * 2 + 2;

    {
        const int row = tid >> 4;
        const int cq  = tid & 15;
#pragma unroll
        for (int i = 0; i < 8; i++) {
            int r = row + i * 8;
            CP_ASYNC(sQ + (r * ROWQ + cq * 8) * 2, Qg + (size_t)r * DIM + cq * 8);
        }
#pragma unroll
        for (int i = 0; i < 4; i++) {
            int r = row + i * 8;
            CP_ASYNC(sK[0] + (r * ROWQ + cq * 8) * 2, Kg + (size_t)r * DIM + cq * 8);
            CP_ASYNC(sV[0] + (r * ROWQ + cq * 8) * 2, Vg + (size_t)r * DIM + cq * 8);
        }
        CP_COMMIT();
#pragma unroll
        for (int i = 0; i < 4; i++) {
            int r = row + i * 8;
            CP_ASYNC(sK[1] + (r * ROWQ + cq * 8) * 2,
                     Kg + (size_t)(32 + r) * DIM + cq * 8);
            CP_ASYNC(sV[1] + (r * ROWQ + cq * 8) * 2,
                     Vg + (size_t)(32 + r) * DIM + cq * 8);
        }
        CP_COMMIT();
    }

    const int grp = lane >> 3;
    const int li  = lane & 7;
    const int r0 = m0 + wid * 16 + (lane >> 2);
    const int r1 = r0 + 8;

    float Of[16][4];
#pragma unroll
    for (int j = 0; j < 16; j++)
#pragma unroll
        for (int e = 0; e < 4; e++) Of[j][e] = 0.0f;
    float mx0 = -1e30f, mx1 = -1e30f, l0 = 0.0f, l1 = 0.0f;

    const int vkey = ((lane >> 3) & 1) * 8 + (lane & 7);
    const int vdof = (lane >> 4) * 8;

    uint32_t qf[8][4];

#pragma unroll 1
    for (int t = 0; t < T; t++) {
        if (t + 1 < T) CP_WAIT1(); else CP_WAIT0();
        __syncthreads();

        if (t == 0) {
#pragma unroll
            for (int ks = 0; ks < 8; ks++)
                LDSM_X4(qf[ks][0], qf[ks][1], qf[ks][2], qf[ks][3],
                        sQ + (((wid * 16 + (grp & 1) * 8 + li)) * ROWQ
                              + ks * 16 + (grp >> 1) * 8) * 2);
        }

        const int n0 = t * BN2;
        if (n0 <= m0 + wid * 16 + 15) {
            const uint32_t kb = sK[t & 1];
            const uint32_t vb = sV[t & 1];

            float sf[4][4];
#pragma unroll
            for (int f = 0; f < 4; f++)
#pragma unroll
                for (int e = 0; e < 4; e++) sf[f][e] = 0.0f;

#pragma unroll
            for (int ks = 0; ks < 8; ks++) {
#pragma unroll
                for (int p = 0; p < 2; p++) {
                    uint32_t b0, b1, b2, b3;
                    LDSM_X4(b0, b1, b2, b3,
                            kb + (((grp >> 1) * 8 + li + p * 16) * ROWQ
                                  + ks * 16 + (grp & 1) * 8) * 2);
                    MMA_F16(sf[2 * p],     qf[ks][0], qf[ks][1], qf[ks][2], qf[ks][3], b0, b1);
                    MMA_F16(sf[2 * p + 1], qf[ks][0], qf[ks][1], qf[ks][2], qf[ks][3], b2, b3);
                }
            }

            if (n0 + 31 > m0 + wid * 16) {
#pragma unroll
                for (int f = 0; f < 4; f++) {
                    int c0 = n0 + f * 8 + (lane & 3) * 2;
                    if (c0 > r0)     sf[f][0] = -1e30f;
                    if (c0 + 1 > r0) sf[f][1] = -1e30f;
                    if (c0 > r1)     sf[f][2] = -1e30f;
                    if (c0 + 1 > r1) sf[f][3] = -1e30f;
                }
            }

            float mt0 = -1e30f, mt1 = -1e30f;
#pragma unroll
            for (int f = 0; f < 4; f++) {
                mt0 = fmaxf(mt0, fmaxf(sf[f][0], sf[f][1]));
                mt1 = fmaxf(mt1, fmaxf(sf[f][2], sf[f][3]));
            }
            mt0 = fmaxf(mt0, __shfl_xor_sync(0xffffffffu, mt0, 1));
            mt0 = fmaxf(mt0, __shfl_xor_sync(0xffffffffu, mt0, 2));
            mt1 = fmaxf(mt1, __shfl_xor_sync(0xffffffffu, mt1, 1));
            mt1 = fmaxf(mt1, __shfl_xor_sync(0xffffffffu, mt1, 2));

            float mn0 = fmaxf(mx0, mt0);
            float mn1 = fmaxf(mx1, mt1);
            float al0 = exp2f(mx0 - mn0);
            float al1 = exp2f(mx1 - mn1);
            mx0 = mn0; mx1 = mn1;

#pragma unroll
            for (int f = 0; f < 4; f++) {
                sf[f][0] = exp2f(sf[f][0] - mn0);
                sf[f][1] = exp2f(sf[f][1] - mn0);
                sf[f][2] = exp2f(sf[f][2] - mn1);
                sf[f][3] = exp2f(sf[f][3] - mn1);
            }

            uint32_t p16[8];
            float lacc[4] = {0.f, 0.f, 0.f, 0.f};
#pragma unroll
            for (int ks2 = 0; ks2 < 2; ks2++) {
                uint32_t pa0 = packh2(sf[2 * ks2][0],     sf[2 * ks2][1]);
                uint32_t pa1 = packh2(sf[2 * ks2][2],     sf[2 * ks2][3]);
                uint32_t pa2 = packh2(sf[2 * ks2 + 1][0], sf[2 * ks2 + 1][1]);
                uint32_t pa3 = packh2(sf[2 * ks2 + 1][2], sf[2 * ks2 + 1][3]);
                p16[ks2 * 4 + 0] = pa0; p16[ks2 * 4 + 1] = pa1;
                p16[ks2 * 4 + 2] = pa2; p16[ks2 * 4 + 3] = pa3;
                MMA_F16(lacc, pa0, pa1, pa2, pa3, ONES, ONES);
            }
            l0 = l0 * al0 + lacc[0];
            l1 = l1 * al1 + lacc[2];

#pragma unroll
            for (int j = 0; j < 16; j++) {
                Of[j][0] *= al0; Of[j][1] *= al0;
                Of[j][2] *= al1; Of[j][3] *= al1;
            }

#pragma unroll
            for (int ks2 = 0; ks2 < 2; ks2++) {
#pragma unroll
                for (int p = 0; p < 8; p++) {
                    uint32_t b0, b1, b2, b3;
                    LDSM_X4_T(b0, b1, b2, b3,
                              vb + ((ks2 * 16 + vkey) * ROWQ + p * 16 + vdof) * 2);
                    MMA_F16(Of[2 * p],     p16[ks2 * 4 + 0], p16[ks2 * 4 + 1],
                            p16[ks2 * 4 + 2], p16[ks2 * 4 + 3], b0, b1);
                    MMA_F16(Of[2 * p + 1], p16[ks2 * 4 + 0], p16[ks2 * 4 + 1],
                            p16[ks2 * 4 + 2], p16[ks2 * 4 + 3], b2, b3);
                }
            }
        }

        __syncthreads();
        if (t + 2 < T) {
            const int nn = (t + 2) * BN2;
            const int row = tid >> 4;
            const int cq  = tid & 15;
            const uint32_t kb2 = sK[t & 1];
            const uint32_t vb2 = sV[t & 1];
#pragma unroll
            for (int i = 0; i < 4; i++) {
                int r = row + i * 8;
                CP_ASYNC(kb2 + (r * ROWQ + cq * 8) * 2,
                         Kg + (size_t)(nn + r) * DIM + cq * 8);
                CP_ASYNC(vb2 + (r * ROWQ + cq * 8) * 2,
                         Vg + (size_t)(nn + r) * DIM + cq * 8);
            }
            CP_COMMIT();
        }
    }

    float inv0 = 1.0f / l0;
    float inv1 = 1.0f / l1;
#pragma unroll
    for (int j = 0; j < 16; j++) {
        int c = h * HDIM + j * 8 + (lane & 3) * 2;
        __half2 o0 = __floats2half2_rn(Of[j][0] * inv0, Of[j][1] * inv0);
        __half2 o1 = __floats2half2_rn(Of[j][2] * inv1, Of[j][3] * inv1);
        *(uint32_t*)&Yh[(bS + r0) * DIM + c] = *(uint32_t*)&o0;
        *(uint32_t*)&Yh[(bS + r1) * DIM + c] = *(uint32_t*)&o1;
    }
}

// ---------------------------------------------------------------------------
extern "C" void kernel_launch(void* const* d_in, const int* in_sizes, int n_in,
                              void* d_out, int out_size)
{
    const float* x  = (const float*)d_in[0];
    const float* Wq = (const float*)d_in[1];
    const float* Wk = (const float*)d_in[2];
    const float* Wv = (const float*)d_in[3];
    const float* Wo = (const float*)d_in[4];
    float* out = (float*)d_out;

    __half* xh;  cudaGetSymbolAddress((void**)&xh,  g_xh);
    __half* woh; cudaGetSymbolAddress((void**)&woh, g_Woh);
    __half* vh;  cudaGetSymbolAddress((void**)&vh,  g_Vh);
    __half* yh;  cudaGetSymbolAddress((void**)&yh,  g_Yh);
    __half* qh;  cudaGetSymbolAddress((void**)&qh,  g_Qh);
    __half* kh;  cudaGetSymbolAddress((void**)&kh,  g_Kh);
    float2* cs;  cudaGetSymbolAddress((void**)&cs,  g_cs);

    cudaFuncSetAttribute(gemm_qkv, cudaFuncAttributeMaxDynamicSharedMemorySize, SMEM_BYTES);
    cudaFuncSetAttribute(gemm_nt,  cudaFuncAttributeMaxDynamicSharedMemorySize, SMEM_BYTES);
    cudaFuncSetAttribute(attn_tc,  cudaFuncAttributeMaxDynamicSharedMemorySize, ATT_SMEM);

    const int nW4 = DIM * DIM / 4;
    const int nX4 = MTOT * DIM / 4;
    // 4 float4 per thread: grid.x covers nX4/4
    f2h_all<<<dim3((nX4 / 4 + 255) / 256, 6), 256>>>(x, Wq, Wk, Wv, Wo, nW4, nX4);

    dim3 gQKV(48, MTOT / 128);
    gemm_qkv<<<gQKV, 256, SMEM_BYTES>>>(xh, cs);

    dim3 gAttn(SEQ / 64, NHEAD, BATCH);
    attn_tc<<<gAttn, 128, ATT_SMEM>>>(qh, kh, vh, yh);

    dim3 gO(DIM / 128, MTOT / 128);
    gemm_nt<<<gO, 256, SMEM_BYTES>>>(yh, woh, out);
}

// round 15
// speedup vs baseline: 1.0125x; 1.0014x over previous
#include <cuda_runtime.h>
#include <cuda_fp16.h>
#include <math.h>
#include <stdint.h>

#define BATCH 2
#define SEQ   2048
#define DIM   2048
#define NHEAD 16
#define HDIM  128
#define MTOT  (BATCH * SEQ)
#define EPSV  1.1920928955078125e-07f
#define LOG2E 1.4426950408889634f

// fp16 operands / intermediates
__device__ __half g_xh[MTOT * DIM];
__device__ __half g_Wqh[DIM * DIM];   // rows permuted per head (rope pairing)
__device__ __half g_Wkh[DIM * DIM];
__device__ __half g_Wvh[DIM * DIM];
__device__ __half g_Woh[DIM * DIM];
__device__ __half g_Vh[MTOT * DIM];
__device__ __half g_Yh[MTOT * DIM];
__device__ __half g_Qh[MTOT * DIM];
__device__ __half g_Kh[MTOT * DIM];
__device__ float2 g_cs[SEQ * 64];

// ---------------------------------------------------------------------------
// Conversions + rope table, 4 float4 per thread (MLP=4):
// y<4 -> weights (Wq/Wk permuted), y==4 -> x, y==5 -> rope cos/sin table
// ---------------------------------------------------------------------------
__global__ void f2h_all(const float* __restrict__ x,
                        const float* __restrict__ w0, const float* __restrict__ w1,
                        const float* __restrict__ w2, const float* __restrict__ w3,
                        int nW4, int nX4)
{
    const int which = blockIdx.y;
    const int stride = gridDim.x * blockDim.x;
    const int base = blockIdx.x * blockDim.x + threadIdx.x;

    if (which == 5) {
#pragma unroll
        for (int k = 0; k < 4; k++) {
            int i = base + k * stride;
            if (i >= SEQ * 64) break;
            int pos = i >> 6;
            int p   = i & 63;
            const float LN1E4 = 9.210340371976184f;
            float ang = (float)pos * __expf(-(float)p * (1.0f / 64.0f) * LN1E4);
            float sn, cn;
            sincosf(ang, &sn, &cn);
            g_cs[i] = make_float2(cn, sn);
        }
        return;
    }

    const float* s;
    __half* d;
    int n4;
    if (which == 4) {
        s = x; d = g_xh; n4 = nX4;
    } else {
        s = (which == 0) ? w0 : (which == 1) ? w1 : (which == 2) ? w2 : w3;
        d = (which == 0) ? g_Wqh : (which == 1) ? g_Wkh
          : (which == 2) ? g_Wvh : g_Woh;
        n4 = nW4;
    }

    float4 v[4];
    int idx[4];
    int cnt = 0;
#pragma unroll
    for (int k = 0; k < 4; k++) {
        int i = base + k * stride;
        if (i < n4) {
            int src = i;
            if (which < 2) {
                int rd = i >> 9;
                int c4 = i & 511;
                int head = rd >> 7;
                int m = rd & 127;
                int od = (m & 1) ? (m >> 1) + 64 : (m >> 1);
                src = (head * 128 + od) * 512 + c4;
            }
            v[cnt] = ((const float4*)s)[src];
            idx[cnt] = i;
            cnt++;
        }
    }
#pragma unroll
    for (int k = 0; k < 4; k++) {
        if (k < cnt) {
            __half2 a = __floats2half2_rn(v[k].x, v[k].y);
            __half2 b = __floats2half2_rn(v[k].z, v[k].w);
            uint2 o;
            o.x = *(uint32_t*)&a;
            o.y = *(uint32_t*)&b;
            ((uint2*)d)[idx[k]] = o;
        }
    }
}

// ---------------------------------------------------------------------------
// PTX helpers
// ---------------------------------------------------------------------------
__device__ __forceinline__ uint32_t smem_u32(const void* p) {
    uint32_t a;
    asm("{ .reg .u64 t; cvta.to.shared.u64 t, %1; cvt.u32.u64 %0, t; }"
        : "=r"(a) : "l"(p));
    return a;
}
#define CP_ASYNC(saddr, gaddr) \
    asm volatile("cp.async.cg.shared.global [%0], [%1], 16;" :: "r"(saddr), "l"(gaddr))
#define CP_COMMIT() asm volatile("cp.async.commit_group;" ::: "memory")
#define CP_WAIT1()  asm volatile("cp.async.wait_group 1;" ::: "memory")
#define CP_WAIT0()  asm volatile("cp.async.wait_group 0;" ::: "memory")
#define LDSM_X4(r0, r1, r2, r3, addr) \
    asm volatile("ldmatrix.sync.aligned.m8n8.x4.shared.b16 {%0,%1,%2,%3}, [%4];" \
        : "=r"(r0), "=r"(r1), "=r"(r2), "=r"(r3) : "r"(addr))
#define LDSM_X4_T(r0, r1, r2, r3, addr) \
    asm volatile("ldmatrix.sync.aligned.m8n8.x4.trans.shared.b16 {%0,%1,%2,%3}, [%4];" \
        : "=r"(r0), "=r"(r1), "=r"(r2), "=r"(r3) : "r"(addr))
#define MMA_F16(c, a0, a1, a2, a3, b0, b1) \
    asm volatile("mma.sync.aligned.m16n8k16.row.col.f32.f16.f16.f32 " \
        "{%0,%1,%2,%3}, {%4,%5,%6,%7}, {%8,%9}, {%0,%1,%2,%3};" \
        : "+f"((c)[0]), "+f"((c)[1]), "+f"((c)[2]), "+f"((c)[3]) \
        : "r"(a0), "r"(a1), "r"(a2), "r"(a3), "r"(b0), "r"(b1))

__device__ __forceinline__ uint32_t packh2(float x, float y) {
    __half2 h = __floats2half2_rn(x, y);
    return *(uint32_t*)&h;
}

// ===========================================================================
// fp16 GEMM (champion config): block 128x128, BK=32, 8 warps (4x2),
// warp tile 32x64, 3-stage cp.async, single barrier per k-iter.
// ===========================================================================
#define BK       32
#define ROWP     40
#define STAGE_H  (128 * ROWP)
#define NSTAGE   3
#define SMEM_BYTES (NSTAGE * 2 * STAGE_H * 2)   // 61440

__device__ __forceinline__ void gemm_issue(const __half* __restrict__ A,
                                           const __half* __restrict__ B,
                                           uint32_t sA, uint32_t sB,
                                           int m0, int n0, int kt, int tid)
{
    const int row = tid >> 1;
    const int cb  = (tid & 1) * 2;
#pragma unroll
    for (int c = 0; c < 2; c++) {
        int col = (cb + c) * 8;
        CP_ASYNC(sA + (row * ROWP + col) * 2,
                 A + (size_t)(m0 + row) * DIM + kt * BK + col);
        CP_ASYNC(sB + (row * ROWP + col) * 2,
                 B + (size_t)(n0 + row) * DIM + kt * BK + col);
    }
    CP_COMMIT();
}

__device__ __forceinline__ void gemm_compute(uint32_t sA, uint32_t sB,
                                             float c[2][8][4],
                                             int wm, int wn, int lane)
{
    const int grp = lane >> 3;
    const int li  = lane & 7;
    const int arow = wm * 32 + (grp & 1) * 8 + li;
    const int akof = (grp >> 1) * 8;
    const int brow = wn * 64 + (grp >> 1) * 8 + li;
    const int bkof = (grp & 1) * 8;

#pragma unroll
    for (int ks = 0; ks < 2; ks++) {
        uint32_t a[2][4];
        uint32_t b[4][4];
#pragma unroll
        for (int i = 0; i < 2; i++)
            LDSM_X4(a[i][0], a[i][1], a[i][2], a[i][3],
                    sA + ((arow + i * 16) * ROWP + ks * 16 + akof) * 2);
#pragma unroll
        for (int p = 0; p < 4; p++)
            LDSM_X4(b[p][0], b[p][1], b[p][2], b[p][3],
                    sB + ((brow + p * 16) * ROWP + ks * 16 + bkof) * 2);
#pragma unroll
        for (int i = 0; i < 2; i++)
#pragma unroll
            for (int j = 0; j < 8; j++)
                MMA_F16(c[i][j], a[i][0], a[i][1], a[i][2], a[i][3],
                        b[j >> 1][(j & 1) * 2 + 0], b[j >> 1][(j & 1) * 2 + 1]);
    }
}

// MODE 0: fp32 out; MODE 1: fp16 out; MODE 2: fp16 out + RMSNorm + RoPE
template <int MODE>
__device__ __forceinline__ void gemm_body(const __half* __restrict__ A,
                                          const __half* __restrict__ B,
                                          float* __restrict__ C,
                                          __half* __restrict__ Ch,
                                          float oscale,
                                          const float2* __restrict__ cs,
                                          int m0, int n0)
{
    extern __shared__ __half sh[];
    const int tid  = threadIdx.x;
    const int lane = tid & 31;
    const int wid  = tid >> 5;
    const int wm   = wid >> 1;
    const int wn   = wid & 1;

    uint32_t sA[NSTAGE], sB[NSTAGE];
#pragma unroll
    for (int s = 0; s < NSTAGE; s++) {
        sA[s] = smem_u32(sh + s * 2 * STAGE_H);
        sB[s] = smem_u32(sh + s * 2 * STAGE_H + STAGE_H);
    }

    float c[2][8][4];
#pragma unroll
    for (int i = 0; i < 2; i++)
#pragma unroll
        for (int j = 0; j < 8; j++)
#pragma unroll
            for (int e = 0; e < 4; e++) c[i][j][e] = 0.0f;

    const int NIT = DIM / BK;   // 64

    gemm_issue(A, B, sA[0], sB[0], m0, n0, 0, tid);
    gemm_issue(A, B, sA[1], sB[1], m0, n0, 1, tid);

#pragma unroll 1
    for (int kt = 0; kt < NIT; kt++) {
        if (kt + 2 < NIT) CP_WAIT1(); else CP_WAIT0();
        __syncthreads();
        if (kt + 2 < NIT)
            gemm_issue(A, B, sA[(kt + 2) % 3], sB[(kt + 2) % 3],
                       m0, n0, kt + 2, tid);
        gemm_compute(sA[kt % 3], sB[kt % 3], c, wm, wn, lane);
    }

    const int g = lane >> 2;
    const int t = lane & 3;

    if (MODE == 2) {
        __syncthreads();
        float* fss = (float*)sh;
        float ssp[2][2];
#pragma unroll
        for (int i = 0; i < 2; i++) {
            float slo = 0.f, shi = 0.f;
#pragma unroll
            for (int j = 0; j < 8; j++) {
                slo += c[i][j][0] * c[i][j][0] + c[i][j][1] * c[i][j][1];
                shi += c[i][j][2] * c[i][j][2] + c[i][j][3] * c[i][j][3];
            }
            slo += __shfl_xor_sync(0xffffffffu, slo, 1);
            slo += __shfl_xor_sync(0xffffffffu, slo, 2);
            shi += __shfl_xor_sync(0xffffffffu, shi, 1);
            shi += __shfl_xor_sync(0xffffffffu, shi, 2);
            ssp[i][0] = slo; ssp[i][1] = shi;
        }
        if (t == 0) {
#pragma unroll
            for (int i = 0; i < 2; i++) {
                int rb = wm * 32 + i * 16 + g;
                fss[wn * 128 + rb]     = ssp[i][0];
                fss[wn * 128 + rb + 8] = ssp[i][1];
            }
        }
        __syncthreads();
#pragma unroll
        for (int i = 0; i < 2; i++) {
            int rlo = wm * 32 + i * 16 + g;
            int rhi = rlo + 8;
            float rnlo = rsqrtf((fss[rlo] + fss[128 + rlo]) * (1.0f / 128.0f) + EPSV) * oscale;
            float rnhi = rsqrtf((fss[rhi] + fss[128 + rhi]) * (1.0f / 128.0f) + EPSV) * oscale;
            int poslo = (m0 + rlo) & (SEQ - 1);
            int poshi = (m0 + rhi) & (SEQ - 1);
#pragma unroll
            for (int j = 0; j < 8; j++) {
                int dp = wn * 32 + j * 4 + t;
                int ncol = n0 + wn * 64 + j * 8 + t * 2;
                float2 cl = cs[poslo * 64 + dp];
                float x1 = c[i][j][0] * rnlo, x2 = c[i][j][1] * rnlo;
                uint32_t olo = packh2(x1 * cl.x + x2 * cl.y,
                                      -x1 * cl.y + x2 * cl.x);
                *(uint32_t*)&Ch[(size_t)(m0 + rlo) * DIM + ncol] = olo;
                float2 ch2 = cs[poshi * 64 + dp];
                float y1 = c[i][j][2] * rnhi, y2 = c[i][j][3] * rnhi;
                uint32_t ohi = packh2(y1 * ch2.x + y2 * ch2.y,
                                      -y1 * ch2.y + y2 * ch2.x);
                *(uint32_t*)&Ch[(size_t)(m0 + rhi) * DIM + ncol] = ohi;
            }
        }
        return;
    }

#pragma unroll
    for (int i = 0; i < 2; i++) {
        int mbase = m0 + wm * 32 + i * 16;
#pragma unroll
        for (int j = 0; j < 8; j++) {
            int ncol = n0 + wn * 64 + j * 8 + t * 2;
            if (MODE == 1) {
                uint32_t lo = packh2(c[i][j][0], c[i][j][1]);
                uint32_t hi = packh2(c[i][j][2], c[i][j][3]);
                *(uint32_t*)&Ch[(size_t)(mbase + g) * DIM + ncol]     = lo;
                *(uint32_t*)&Ch[(size_t)(mbase + g + 8) * DIM + ncol] = hi;
            } else {
                *(float2*)&C[(size_t)(mbase + g) * DIM + ncol] =
                    make_float2(c[i][j][0], c[i][j][1]);
                *(float2*)&C[(size_t)(mbase + g + 8) * DIM + ncol] =
                    make_float2(c[i][j][2], c[i][j][3]);
            }
        }
    }
}

// QKV fused: grid.x = 48: [0,16)->Q, [16,32)->K, [32,48)->V
__global__ __launch_bounds__(256, 2) void gemm_qkv(const __half* __restrict__ xh,
                                                   const float2* __restrict__ cs)
{
    const int which = blockIdx.x >> 4;
    const int n0 = (blockIdx.x & 15) * 128;
    const int m0 = blockIdx.y * 128;
    const float QSC = 0.08838834764831845f * LOG2E;
    if (which == 0)
        gemm_body<2>(xh, g_Wqh, nullptr, g_Qh, QSC, cs, m0, n0);
    else if (which == 1)
        gemm_body<2>(xh, g_Wkh, nullptr, g_Kh, 1.0f, cs, m0, n0);
    else
        gemm_body<1>(xh, g_Wvh, nullptr, g_Vh, 1.0f, nullptr, m0, n0);
}

__global__ __launch_bounds__(256, 2) void gemm_nt(const __half* __restrict__ A,
                                                  const __half* __restrict__ B,
                                                  float* __restrict__ C)
{
    gemm_body<0>(A, B, C, nullptr, 1.0f, nullptr, blockIdx.y * 128, blockIdx.x * 128);
}

// ===========================================================================
// Tensor-core causal flash attention (champion): 64 q-rows/CTA, 4 warps,
// BN=32 double-buffered, 3 CTAs/SM. Heavy-first order, Q frags in registers,
// row sums via all-ones MMA.
// ===========================================================================
#define BN2    32
#define ROWQ   136
#define A_QH   (64 * ROWQ)
#define A_KH   (32 * ROWQ)
#define A_K0   (A_QH)
#define A_K1   (A_QH + A_KH)
#define A_V0   (A_QH + 2 * A_KH)
#define A_V1   (A_QH + 3 * A_KH)
#define ATT_SMEM ((A_QH + 4 * A_KH) * 2)   // 52224 bytes

__global__ __launch_bounds__(128, 3) void attn_tc(const __half* __restrict__ Qh,
                                                  const __half* __restrict__ Kh,
                                                  const __half* __restrict__ Vh,
                                                  __half* __restrict__ Yh)
{
    extern __shared__ __half ash[];
    const int tid  = threadIdx.x;
    const int lane = tid & 31;
    const int wid  = tid >> 5;
    const int b = blockIdx.z;
    const int h = blockIdx.y;
    const int bx = (int)gridDim.x - 1 - (int)blockIdx.x;
    const int m0 = bx * 64;
    const size_t bS = (size_t)b * SEQ;
    const uint32_t ONES = 0x3C003C00u;

    const uint32_t sQ = smem_u32(ash);
    uint32_t sK[2] = { smem_u32(ash + A_K0), smem_u32(ash + A_K1) };
    uint32_t sV[2] = { smem_u32(ash + A_V0), smem_u32(ash + A_V1) };

    const __half* Qg = Qh + (bS + m0) * DIM + h * HDIM;
    const __half* Kg = Kh + bS * DIM + h * HDIM;
    const __half* Vg = Vh + bS * DIM + h * HDIM;

    const int T = bx * 2 + 2;

    {
        const int row = tid >> 4;
        const int cq  = tid & 15;
#pragma unroll
        for (int i = 0; i < 8; i++) {
            int r = row + i * 8;
            CP_ASYNC(sQ + (r * ROWQ + cq * 8) * 2, Qg + (size_t)r * DIM + cq * 8);
        }
#pragma unroll
        for (int i = 0; i < 4; i++) {
            int r = row + i * 8;
            CP_ASYNC(sK[0] + (r * ROWQ + cq * 8) * 2, Kg + (size_t)r * DIM + cq * 8);
            CP_ASYNC(sV[0] + (r * ROWQ + cq * 8) * 2, Vg + (size_t)r * DIM + cq * 8);
        }
        CP_COMMIT();
#pragma unroll
        for (int i = 0; i < 4; i++) {
            int r = row + i * 8;
            CP_ASYNC(sK[1] + (r * ROWQ + cq * 8) * 2,
                     Kg + (size_t)(32 + r) * DIM + cq * 8);
            CP_ASYNC(sV[1] + (r * ROWQ + cq * 8) * 2,
                     Vg + (size_t)(32 + r) * DIM + cq * 8);
        }
        CP_COMMIT();
    }

    const int grp = lane >> 3;
    const int li  = lane & 7;
    const int r0 = m0 + wid * 16 + (lane >> 2);
    const int r1 = r0 + 8;

    float Of[16][4];
#pragma unroll
    for (int j = 0; j < 16; j++)
#pragma unroll
        for (int e = 0; e < 4; e++) Of[j][e] = 0.0f;
    float mx0 = -1e30f, mx1 = -1e30f, l0 = 0.0f, l1 = 0.0f;

    const int vkey = ((lane >> 3) & 1) * 8 + (lane & 7);
    const int vdof = (lane >> 4) * 8;

    uint32_t qf[8][4];

#pragma unroll 1
    for (int t = 0; t < T; t++) {
        if (t + 1 < T) CP_WAIT1(); else CP_WAIT0();
        __syncthreads();

        if (t == 0) {
#pragma unroll
            for (int ks = 0; ks < 8; ks++)
                LDSM_X4(qf[ks][0], qf[ks][1], qf[ks][2], qf[ks][3],
                        sQ + (((wid * 16 + (grp & 1) * 8 + li)) * ROWQ
                              + ks * 16 + (grp >> 1) * 8) * 2);
        }

        const int n0 = t * BN2;
        if (n0 <= m0 + wid * 16 + 15) {
            const uint32_t kb = sK[t & 1];
            const uint32_t vb = sV[t & 1];

            float sf[4][4];
#pragma unroll
            for (int f = 0; f < 4; f++)
#pragma unroll
                for (int e = 0; e < 4; e++) sf[f][e] = 0.0f;

#pragma unroll
            for (int ks = 0; ks < 8; ks++) {
#pragma unroll
                for (int p = 0; p < 2; p++) {
                    uint32_t b0, b1, b2, b3;
                    LDSM_X4(b0, b1, b2, b3,
                            kb + (((grp >> 1) * 8 + li + p * 16) * ROWQ
                                  + ks * 16 + (grp & 1) * 8) * 2);
                    MMA_F16(sf[2 * p],     qf[ks][0], qf[ks][1], qf[ks][2], qf[ks][3], b0, b1);
                    MMA_F16(sf[2 * p + 1], qf[ks][0], qf[ks][1], qf[ks][2], qf[ks][3], b2, b3);
                }
            }

            if (n0 + 31 > m0 + wid * 16) {
#pragma unroll
                for (int f = 0; f < 4; f++) {
                    int c0 = n0 + f * 8 + (lane & 3) * 2;
                    if (c0 > r0)     sf[f][0] = -1e30f;
                    if (c0 + 1 > r0) sf[f][1] = -1e30f;
                    if (c0 > r1)     sf[f][2] = -1e30f;
                    if (c0 + 1 > r1) sf[f][3] = -1e30f;
                }
            }

            float mt0 = -1e30f, mt1 = -1e30f;
#pragma unroll
            for (int f = 0; f < 4; f++) {
                mt0 = fmaxf(mt0, fmaxf(sf[f][0], sf[f][1]));
                mt1 = fmaxf(mt1, fmaxf(sf[f][2], sf[f][3]));
            }
            mt0 = fmaxf(mt0, __shfl_xor_sync(0xffffffffu, mt0, 1));
            mt0 = fmaxf(mt0, __shfl_xor_sync(0xffffffffu, mt0, 2));
            mt1 = fmaxf(mt1, __shfl_xor_sync(0xffffffffu, mt1, 1));
            mt1 = fmaxf(mt1, __shfl_xor_sync(0xffffffffu, mt1, 2));

            float mn0 = fmaxf(mx0, mt0);
            float mn1 = fmaxf(mx1, mt1);
            float al0 = exp2f(mx0 - mn0);
            float al1 = exp2f(mx1 - mn1);
            mx0 = mn0; mx1 = mn1;

#pragma unroll
            for (int f = 0; f < 4; f++) {
                sf[f][0] = exp2f(sf[f][0] - mn0);
                sf[f][1] = exp2f(sf[f][1] - mn0);
                sf[f][2] = exp2f(sf[f][2] - mn1);
                sf[f][3] = exp2f(sf[f][3] - mn1);
            }

            uint32_t p16[8];
            float lacc[4] = {0.f, 0.f, 0.f, 0.f};
#pragma unroll
            for (int ks2 = 0; ks2 < 2; ks2++) {
                uint32_t pa0 = packh2(sf[2 * ks2][0],     sf[2 * ks2][1]);
                uint32_t pa1 = packh2(sf[2 * ks2][2],     sf[2 * ks2][3]);
                uint32_t pa2 = packh2(sf[2 * ks2 + 1][0], sf[2 * ks2 + 1][1]);
                uint32_t pa3 = packh2(sf[2 * ks2 + 1][2], sf[2 * ks2 + 1][3]);
                p16[ks2 * 4 + 0] = pa0; p16[ks2 * 4 + 1] = pa1;
                p16[ks2 * 4 + 2] = pa2; p16[ks2 * 4 + 3] = pa3;
                MMA_F16(lacc, pa0, pa1, pa2, pa3, ONES, ONES);
            }
            l0 = l0 * al0 + lacc[0];
            l1 = l1 * al1 + lacc[2];

#pragma unroll
            for (int j = 0; j < 16; j++) {
                Of[j][0] *= al0; Of[j][1] *= al0;
                Of[j][2] *= al1; Of[j][3] *= al1;
            }

#pragma unroll
            for (int ks2 = 0; ks2 < 2; ks2++) {
#pragma unroll
                for (int p = 0; p < 8; p++) {
                    uint32_t b0, b1, b2, b3;
                    LDSM_X4_T(b0, b1, b2, b3,
                              vb + ((ks2 * 16 + vkey) * ROWQ + p * 16 + vdof) * 2);
                    MMA_F16(Of[2 * p],     p16[ks2 * 4 + 0], p16[ks2 * 4 + 1],
                            p16[ks2 * 4 + 2], p16[ks2 * 4 + 3], b0, b1);
                    MMA_F16(Of[2 * p + 1], p16[ks2 * 4 + 0], p16[ks2 * 4 + 1],
                            p16[ks2 * 4 + 2], p16[ks2 * 4 + 3], b2, b3);
                }
            }
        }

        __syncthreads();
        if (t + 2 < T) {
            const int nn = (t + 2) * BN2;
            const int row = tid >> 4;
            const int cq  = tid & 15;
            const uint32_t kb2 = sK[t & 1];
            const uint32_t vb2 = sV[t & 1];
#pragma unroll
            for (int i = 0; i < 4; i++) {
                int r = row + i * 8;
                CP_ASYNC(kb2 + (r * ROWQ + cq * 8) * 2,
                         Kg + (size_t)(nn + r) * DIM + cq * 8);
                CP_ASYNC(vb2 + (r * ROWQ + cq * 8) * 2,
                         Vg + (size_t)(nn + r) * DIM + cq * 8);
            }
            CP_COMMIT();
        }
    }

    float inv0 = 1.0f / l0;
    float inv1 = 1.0f / l1;
#pragma unroll
    for (int j = 0; j < 16; j++) {
        int c = h * HDIM + j * 8 + (lane & 3) * 2;
        __half2 o0 = __floats2half2_rn(Of[j][0] * inv0, Of[j][1] * inv0);
        __half2 o1 = __floats2half2_rn(Of[j][2] * inv1, Of[j][3] * inv1);
        *(uint32_t*)&Yh[(bS + r0) * DIM + c] = *(uint32_t*)&o0;
        *(uint32_t*)&Yh[(bS + r1) * DIM + c] = *(uint32_t*)&o1;
    }
}

// ---------------------------------------------------------------------------
extern "C" void kernel_launch(void* const* d_in, const int* in_sizes, int n_in,
                              void* d_out, int out_size)
{
    const float* x  = (const float*)d_in[0];
    const float* Wq = (const float*)d_in[1];
    const float* Wk = (const float*)d_in[2];
    const float* Wv = (const float*)d_in[3];
    const float* Wo = (const float*)d_in[4];
    float* out = (float*)d_out;

    __half* xh;  cudaGetSymbolAddress((void**)&xh,  g_xh);
    __half* woh; cudaGetSymbolAddress((void**)&woh, g_Woh);
    __half* vh;  cudaGetSymbolAddress((void**)&vh,  g_Vh);
    __half* yh;  cudaGetSymbolAddress((void**)&yh,  g_Yh);
    __half* qh;  cudaGetSymbolAddress((void**)&qh,  g_Qh);
    __half* kh;  cudaGetSymbolAddress((void**)&kh,  g_Kh);
    float2* cs;  cudaGetSymbolAddress((void**)&cs,  g_cs);

    cudaFuncSetAttribute(gemm_qkv, cudaFuncAttributeMaxDynamicSharedMemorySize, SMEM_BYTES);
    cudaFuncSetAttribute(gemm_nt,  cudaFuncAttributeMaxDynamicSharedMemorySize, SMEM_BYTES);
    cudaFuncSetAttribute(attn_tc,  cudaFuncAttributeMaxDynamicSharedMemorySize, ATT_SMEM);

    const int nW4 = DIM * DIM / 4;
    const int nX4 = MTOT * DIM / 4;
    f2h_all<<<dim3((nX4 / 4 + 255) / 256, 6), 256>>>(x, Wq, Wk, Wv, Wo, nW4, nX4);

    dim3 gQKV(48, MTOT / 128);
    gemm_qkv<<<gQKV, 256, SMEM_BYTES>>>(xh, cs);

    dim3 gAttn(SEQ / 64, NHEAD, BATCH);
    attn_tc<<<gAttn, 128, ATT_SMEM>>>(qh, kh, vh, yh);

    dim3 gO(DIM / 128, MTOT / 128);
    gemm_nt<<<gO, 256, SMEM_BYTES>>>(yh, woh, out);
}